// round 11
// baseline (speedup 1.0000x reference)
#include <cuda_runtime.h>
#include <cuda_fp16.h>

#define FLAT 12288
#define HID  4096
#define NS   16
#define KST  4
#define LRf  0.01f
#define RCH1 96          // chunks in fused fp32 conv pass (128 rows each)
#define RCH2 192         // chunks in fp16 gemvT passes (64 rows each)
#define CTH  1024        // threads per CTA (cheap phase)
#define NC   8           // cluster CTAs (cheap phase)
#define GS   (NC * CTH)  // global stride in cheap phase

// ---------------- device scratch (static, no runtime allocation) ----------------
__device__ __half g_Wh[(size_t)FLAT * HID];  // fp16 copy of W (96 MB)
__device__ float g_part[RCH2 * HID];  // gemvT partial column sums
__device__ float g_h[HID];            // dense-phase working h
__device__ float g_hA[HID];           // hinit_0 (q)
__device__ float g_hB[HID];           // hfinal_0 (s)
__device__ float g_hC[HID];           // pong q
__device__ float g_hD[HID];           // pong s
__device__ float g_vA[FLAT];          // vfinal_0 / r ping
__device__ float g_vB[FLAT];          // r pong
__device__ float g_dp[2][2 * NC];     // cross-CTA dot partials (double-buffered)

__device__ __forceinline__ float sigm(float x) { return 1.f / (1.f + __expf(-x)); }

// ---------------- dense phase: sample 0 ----------------

// Pass 1 of gemvT, fused with W->fp16 conversion: reads fp32 W (200MB) once,
// emits fp16 copy (100MB) and partial column sums. 128-row chunks, grid (8,96).
__global__ void k_gemvT_conv(const float* __restrict__ W, const float* __restrict__ v) {
    __shared__ float sv[128];
    int r0 = blockIdx.y * 128;
    if (threadIdx.x < 128) sv[threadIdx.x] = v[r0 + threadIdx.x];
    __syncthreads();
    int col2 = blockIdx.x * 256 + threadIdx.x;      // float2/half2 column index
    const float2* Wp = (const float2*)W + (size_t)r0 * (HID / 2) + col2;
    __half2* Whp = (__half2*)g_Wh + (size_t)r0 * (HID / 2) + col2;
    float ax = 0.f, ay = 0.f;
#pragma unroll 8
    for (int r = 0; r < 128; r++) {
        float2 w = Wp[(size_t)r * (HID / 2)];
        Whp[(size_t)r * (HID / 2)] = __floats2half2_rn(w.x, w.y);
        float s = sv[r];
        ax += w.x * s;
        ay += w.y * s;
    }
    float2 o; o.x = ax; o.y = ay;
    ((float2*)g_part)[blockIdx.y * (HID / 2) + col2] = o;
}

// Passes 2..4: fp16 W, uint2 loads (4 halves = 8B) for 64B-in-flight/thread.
// 64-row chunks, grid (4, 192) = 768 blocks.
__global__ void k_gemvT(const float* __restrict__ v) {
    __shared__ float sv[64];
    int r0 = blockIdx.y * 64;
    if (threadIdx.x < 64) sv[threadIdx.x] = v[r0 + threadIdx.x];
    __syncthreads();
    int col4 = blockIdx.x * 256 + threadIdx.x;      // 4-half group index
    const uint2* Wp = (const uint2*)g_Wh + (size_t)r0 * (HID / 4) + col4;
    float a0 = 0.f, a1 = 0.f, a2 = 0.f, a3 = 0.f;
#pragma unroll 8
    for (int r = 0; r < 64; r++) {
        uint2 wv = Wp[(size_t)r * (HID / 4)];
        float2 f0 = __half22float2(*reinterpret_cast<__half2*>(&wv.x));
        float2 f1 = __half22float2(*reinterpret_cast<__half2*>(&wv.y));
        float s = sv[r];
        a0 += f0.x * s; a1 += f0.y * s; a2 += f1.x * s; a3 += f1.y * s;
    }
    float4 o; o.x = a0; o.y = a1; o.z = a2; o.w = a3;
    ((float4*)g_part)[blockIdx.y * (HID / 4) + col4] = o;
}

// reduce partials + bias + sigmoid -> g_h; optionally save hinit/hfinal
__global__ void k_hred(const float* __restrict__ b, int save, int nch) {
    int j = blockIdx.x * 256 + threadIdx.x;
    float s = b[j];
    for (int r = 0; r < nch; r++) s += g_part[r * HID + j];
    float h = sigm(s);
    g_h[j] = h;
    if (save == 1) g_hA[j] = h;        // hinit_0 (q for sample 1)
    else if (save == 2) g_hB[j] = h;   // hfinal_0 (s for sample 1)
}

// v = sigmoid(a + W h): one warp per row, 16 rows per 512-thread block.
// uint4 loads = 8 halves per LDG (16B).
__global__ void k_gemv(const float* __restrict__ a) {
    __shared__ float sh[HID];
    for (int k = threadIdx.x; k < HID; k += blockDim.x) sh[k] = g_h[k];
    __syncthreads();
    int warp = threadIdx.x >> 5, lane = threadIdx.x & 31;
    int row = blockIdx.x * 16 + warp;
    const uint4* Wr = (const uint4*)(g_Wh + (size_t)row * HID);   // 8 halves/load
    float acc = 0.f;
#pragma unroll 8
    for (int i = lane; i < HID / 8; i += 32) {
        uint4 wv = Wr[i];
        float2 f0 = __half22float2(*reinterpret_cast<__half2*>(&wv.x));
        float2 f1 = __half22float2(*reinterpret_cast<__half2*>(&wv.y));
        float2 f2 = __half22float2(*reinterpret_cast<__half2*>(&wv.z));
        float2 f3 = __half22float2(*reinterpret_cast<__half2*>(&wv.w));
        float4 h0 = *(const float4*)&sh[8 * i];
        float4 h1 = *(const float4*)&sh[8 * i + 4];
        acc += f0.x * h0.x + f0.y * h0.y + f1.x * h0.z + f1.y * h0.w;
        acc += f2.x * h1.x + f2.y * h1.y + f3.x * h1.z + f3.y * h1.w;
    }
#pragma unroll
    for (int o = 16; o; o >>= 1) acc += __shfl_down_sync(0xffffffffu, acc, o);
    if (lane == 0) g_vA[row] = sigm(a[row] + acc);
}

// ---------------- cheap phase: samples 1..15, rank-2 W, 8-CTA cluster ----------------
// Fixed thread->element mapping: vector elements never cross CTAs (plain ld/st,
// per-CTA slices stay L1-local). Only the two dot scalars cross CTAs via g_dp
// (double-buffered), ordered by the cluster barrier (arrive=release, wait=acquire).

__device__ __forceinline__ float2 clusterdot2(float a, float b, int rank, int par) {
    __shared__ float ra[32], rb[32];
#pragma unroll
    for (int o = 16; o; o >>= 1) {
        a += __shfl_down_sync(0xffffffffu, a, o);
        b += __shfl_down_sync(0xffffffffu, b, o);
    }
    int w = threadIdx.x >> 5;
    if ((threadIdx.x & 31) == 0) { ra[w] = a; rb[w] = b; }
    __syncthreads();
    if (threadIdx.x == 0) {
        float x = 0.f, y = 0.f;
#pragma unroll
        for (int k = 0; k < 32; k++) { x += ra[k]; y += rb[k]; }
        g_dp[par][2 * rank] = x;
        g_dp[par][2 * rank + 1] = y;
        __threadfence();
    }
    asm volatile("barrier.cluster.arrive.aligned;" ::: "memory");
    asm volatile("barrier.cluster.wait.aligned;" ::: "memory");
    float x = 0.f, y = 0.f;
#pragma unroll
    for (int c = 0; c < NC; c++) {
        x += __ldcg(&g_dp[par][2 * c]);
        y += __ldcg(&g_dp[par][2 * c + 1]);
    }
    float2 r; r.x = x; r.y = y;
    return r;
}

__global__ void __launch_bounds__(CTH, 1) __cluster_dims__(NC, 1, 1)
k_cheap(const float* __restrict__ inp, float* __restrict__ out) {
    unsigned rank;
    asm("mov.u32 %0, %%cluster_ctarank;" : "=r"(rank));
    const int gt = (int)rank * CTH + threadIdx.x;
    int par = 0;
    float *qc = g_hA, *sc = g_hB, *qn = g_hC, *sn = g_hD;
    float *rc = g_vA, *vw = g_vB;

    // entry dots: d1 = inputs[0].inputs[1], d2 = vfinal_0.inputs[1]
    float2 dv;
    {
        float a1 = 0.f, a2 = 0.f;
        const float* x0 = inp;
        const float* x1 = inp + FLAT;
        for (int k = gt; k < FLAT; k += GS) {
            float b_ = x1[k];
            a1 += x0[k] * b_;
            a2 += rc[k] * b_;
        }
        dv = clusterdot2(a1, a2, rank, par); par ^= 1;
    }

    for (int i = 1; i < NS; i++) {
        const float* p  = inp + (size_t)(i - 1) * FLAT;   // v_init of prev sample
        const float* pn = inp + (size_t)i * FLAT;         // v_init of this sample
        const float* xn = pn + FLAT;                      // next v_init (guarded)
        for (int t = 1; t <= KST; t++) {
            // ---- h phase: h = sigm(LR*(q*(1+d1) - s*(1+d2))); dots q.h, s.h inline
            float c1 = 1.f + dv.x, c2 = 1.f + dv.y;
            float a3 = 0.f, a4 = 0.f;
            float* ht = (t == 1) ? qn : ((t == KST) ? sn : (float*)0);
            for (int j = gt; j < HID; j += GS) {
                float qj = qc[j], sj = sc[j];
                float h = sigm(LRf * (qj * c1 - sj * c2));
                if (ht) ht[j] = h;
                a3 += qj * h;
                a4 += sj * h;
            }
            float2 dh = clusterdot2(a3, a4, rank, par); par ^= 1;

            // ---- v phase: v = sigm(LR*(p*(1+d3) - r*(1+d4))); next-step dots inline
            float c3 = 1.f + dh.x, c4 = 1.f + dh.y;
            float a1 = 0.f, a2 = 0.f;
            if (t < KST) {
                for (int k = gt; k < FLAT; k += GS) {
                    float pk = p[k], rk = rc[k];
                    float v = sigm(LRf * (pk * c3 - rk * c4));
                    a1 += pk * v;          // p.v for next step
                    a2 += rk * v;          // r.v for next step
                }
            } else if (i < NS - 1) {
                for (int k = gt; k < FLAT; k += GS) {
                    float pk = p[k], rk = rc[k];
                    float v = sigm(LRf * (pk * c3 - rk * c4));
                    vw[k] = v;                         // vfinal_i -> r for next sample
                    float xnk = xn[k];
                    a1 += pn[k] * xnk;                 // inputs[i].inputs[i+1]
                    a2 += v * xnk;                     // vfinal_i.inputs[i+1]
                }
            } else {
                for (int k = gt; k < FLAT; k += GS) {
                    float pk = p[k], rk = rc[k];
                    float v = sigm(LRf * (pk * c3 - rk * c4));
                    out[k] = v;                        // final reconstruction
                }
            }
            dv = clusterdot2(a1, a2, rank, par); par ^= 1;
        }
        // rotate buffers for next sample (identical local swaps in every CTA)
        float* tmp;
        tmp = qc; qc = qn; qn = tmp;
        tmp = sc; sc = sn; sn = tmp;
        tmp = rc; rc = vw; vw = tmp;
    }
}

// ---------------- launch ----------------

extern "C" void kernel_launch(void* const* d_in, const int* in_sizes, int n_in,
                              void* d_out, int out_size) {
    const float* inp = (const float*)d_in[0];  // (16, 64, 64, 3) = 16 x 12288
    const float* W   = (const float*)d_in[1];  // (12288, 4096)
    const float* a   = (const float*)d_in[2];  // (12288, 1)
    const float* b   = (const float*)d_in[3];  // (4096, 1)
    float* out = (float*)d_out;                // (12288, 1)

    float* vA = 0;
    cudaGetSymbolAddress((void**)&vA, g_vA);

    for (int s = 0; s < KST; s++) {
        if (s == 0) {
            dim3 g1(HID / 512, RCH1);
            k_gemvT_conv<<<g1, 256>>>(W, inp);     // fused fp16 conversion
            k_hred<<<HID / 256, 256>>>(b, 1, RCH1);
        } else {
            dim3 g2(HID / 1024, RCH2);
            k_gemvT<<<g2, 256>>>(vA);
            k_hred<<<HID / 256, 256>>>(b, (s == KST - 1) ? 2 : 0, RCH2);
        }
        k_gemv<<<FLAT / 16, 512>>>(a);
    }
    k_cheap<<<NC, CTH>>>(inp, out);
}